// round 2
// baseline (speedup 1.0000x reference)
#include <cuda_runtime.h>
#include <math.h>

#define NN 2048
#define DD 256
#define HH 128
#define GG 8
#define MAXD 128
#define NWRD 64   // 32-bit words per adjacency row (2048 bits)

// ---------------- device scratch (static, no runtime allocation) ----------------
static __device__ unsigned g_adj[NN*NWRD];
static __device__ int      g_deg[NN];
static __device__ int      g_nbr[NN*MAXD];
static __device__ int      g_off[NN+1];
static __device__ int      g_nedges;
static __device__ unsigned g_edges[NN*MAXD];   // packed (u<<16)|v, all directed pairs
static __device__ float    g_V[NN];
static __device__ float    g_ent[NN];
static __device__ float    g_p[NN];
static __device__ float    g_a1[NN];
static __device__ float    g_u[NN*HH];
static __device__ float    g_z[NN*HH];
static __device__ float    g_h[NN*HH];
static __device__ float    g_sc[HH];
static __device__ float    g_sh[HH];
static __device__ float    g_gamma;
static __device__ float    g_loss;
static __device__ unsigned g_sel[NWRD];
static __device__ unsigned g_B2[NN*NWRD];
static __device__ unsigned g_B3[NN*NWRD];

// ---------------- adjacency build ----------------
__global__ void k_zero_adj() {
    int i = blockIdx.x*256 + threadIdx.x;
    if (i < NN*NWRD) g_adj[i] = 0u;
}

__global__ void k_build_adj(const int* __restrict__ ei) {
    int e = blockIdx.x*256 + threadIdx.x;
    if (e >= 32768) return;            // 32768 directed entries (both directions present)
    int u = ei[e];
    int v = ei[32768 + e];
    atomicOr(&g_adj[u*NWRD + (v>>5)], 1u << (v & 31));
}

__global__ void k_post() {
    int i = blockIdx.x*256 + threadIdx.x;
    if (i >= NN) return;
    int cnt = 0;
    for (int w = 0; w < NWRD; w++) {
        unsigned m = g_adj[i*NWRD + w];
        while (m) {
            int b = __ffs(m) - 1;
            m &= m - 1;
            if (cnt < MAXD) g_nbr[i*MAXD + cnt] = w*32 + b;
            cnt++;
        }
    }
    g_deg[i] = cnt;
}

__global__ void k_scan() {
    __shared__ int A[NN], B[NN];
    int tid = threadIdx.x;
    for (int i = tid; i < NN; i += 1024) {
        int d = g_deg[i]; if (d > MAXD) d = MAXD;
        A[i] = d;
    }
    __syncthreads();
    int* cur = A; int* nxt = B;
    for (int off = 1; off < NN; off <<= 1) {
        for (int i = tid; i < NN; i += 1024) {
            int v = cur[i];
            if (i >= off) v += cur[i-off];
            nxt[i] = v;
        }
        __syncthreads();
        int* t = cur; cur = nxt; nxt = t;
    }
    for (int i = tid; i < NN; i += 1024) g_off[i+1] = cur[i];
    if (tid == 0) { g_off[0] = 0; g_nedges = cur[NN-1]; }
}

__global__ void k_fill_edges() {
    int i = blockIdx.x*256 + threadIdx.x;
    if (i >= NN) return;
    int o = g_off[i];
    int dg = g_deg[i]; if (dg > MAXD) dg = MAXD;
    for (int t = 0; t < dg; t++)
        g_edges[o + t] = ((unsigned)i << 16) | (unsigned)g_nbr[i*MAXD + t];
}

// ---------------- V (entropy pre-term) ----------------
__global__ void k_V(const float* __restrict__ x) {
    __shared__ int   snb[MAXD];
    __shared__ int   sdeg;
    __shared__ float red[DD];
    int i = blockIdx.x;
    int d = threadIdx.x;
    if (d == 0) sdeg = g_deg[i];
    __syncthreads();
    int dg = sdeg; if (dg > MAXD) dg = MAXD;
    for (int t = d; t < dg; t += DD) snb[t] = g_nbr[i*MAXD + t];
    __syncthreads();
    float xi = x[i*DD + d];
    float ax = 0.f, axx = 0.f;
    for (int t = 0; t < dg; t++) {
        float v = x[snb[t]*DD + d];
        ax  += v;
        axx += v*v;
    }
    float tt = (float)sdeg*xi*xi - 2.f*xi*ax + axx;
    red[d] = tt*tt;
    __syncthreads();
    for (int s = DD/2; s > 0; s >>= 1) {
        if (d < s) red[d] += red[d+s];
        __syncthreads();
    }
    if (d == 0) g_V[i] = sqrtf(red[0]);
}

// ---------------- per-graph softmax -> ent, gamma ----------------
__global__ void k_softmax(const int* __restrict__ batch) {
    __shared__ float sV[NN];
    __shared__ float red[1024];
    __shared__ unsigned char sB[NN];
    __shared__ float gmax[GG], gsum[GG];
    int tid = threadIdx.x;
    for (int i = tid; i < NN; i += 1024) { sV[i] = g_V[i]; sB[i] = (unsigned char)batch[i]; }
    __syncthreads();
    for (int g = 0; g < GG; g++) {
        float m = -1e30f;
        for (int i = tid; i < NN; i += 1024) if (sB[i] == g) m = fmaxf(m, sV[i]);
        red[tid] = m; __syncthreads();
        for (int s = 512; s > 0; s >>= 1) { if (tid < s) red[tid] = fmaxf(red[tid], red[tid+s]); __syncthreads(); }
        if (tid == 0) gmax[g] = red[0];
        __syncthreads();
    }
    for (int i = tid; i < NN; i += 1024) sV[i] = expf(sV[i] - gmax[sB[i]]);
    __syncthreads();
    for (int g = 0; g < GG; g++) {
        float s = 0.f;
        for (int i = tid; i < NN; i += 1024) if (sB[i] == g) s += sV[i];
        red[tid] = s; __syncthreads();
        for (int st = 512; st > 0; st >>= 1) { if (tid < st) red[tid] += red[tid+st]; __syncthreads(); }
        if (tid == 0) gsum[g] = red[0];
        __syncthreads();
    }
    float acc = 0.f;
    for (int i = tid; i < NN; i += 1024) {
        float P = sV[i] / gsum[sB[i]];
        float e = (P == 0.f) ? 0.f : -P*logf(P);
        g_ent[i] = e;
        acc += e;
    }
    red[tid] = acc; __syncthreads();
    for (int s = 512; s > 0; s >>= 1) { if (tid < s) red[tid] += red[tid+s]; __syncthreads(); }
    if (tid == 0) g_gamma = red[0];
}

// ---------------- GIN layers (all buffers accessed as device globals) ----------------
__global__ void k_agg1() { // a1 = ent + A@ent  (scalar per node)
    int i = blockIdx.x*256 + threadIdx.x;
    if (i >= NN) return;
    int dg = g_deg[i]; if (dg > MAXD) dg = MAXD;
    float a = g_ent[i];
    for (int t = 0; t < dg; t++) a += g_ent[g_nbr[i*MAXD + t]];
    g_a1[i] = a;
}

__global__ void k_lin1(const float* __restrict__ w11, const float* __restrict__ b11) {
    int idx = blockIdx.x*256 + threadIdx.x;
    if (idx >= NN*HH) return;
    int i = idx >> 7, c = idx & 127;
    float v = g_a1[i]*w11[c] + b11[c];
    g_z[idx] = v > 0.f ? v : 0.f;
}

// batchnorm stats over g_z -> fold scale/shift into g_sc/g_sh
__global__ void k_bnstats(const float* __restrict__ g, const float* __restrict__ be) {
    __shared__ float red[256];
    __shared__ float mu_s;
    int c = blockIdx.x, tid = threadIdx.x;
    float s = 0.f;
    for (int r = tid; r < NN; r += 256) s += g_z[r*HH + c];
    red[tid] = s; __syncthreads();
    for (int st = 128; st > 0; st >>= 1) { if (tid < st) red[tid] += red[tid+st]; __syncthreads(); }
    if (tid == 0) mu_s = red[0] / (float)NN;
    __syncthreads();
    float mu = mu_s;
    float s2 = 0.f;
    for (int r = tid; r < NN; r += 256) { float d = g_z[r*HH + c] - mu; s2 += d*d; }
    red[tid] = s2; __syncthreads();
    for (int st = 128; st > 0; st >>= 1) { if (tid < st) red[tid] += red[tid+st]; __syncthreads(); }
    if (tid == 0) {
        float var = red[0] / (float)NN;
        float inv = 1.f / sqrtf(var + 1e-5f);
        float sc  = g[c]*inv;
        g_sc[c] = sc;
        g_sh[c] = be[c] - mu*sc;
    }
}

// g_h = bn(g_z) @ W2 + b2  (affine folded into g_sc/g_sh)
__global__ void k_gemm2(const float* __restrict__ W, const float* __restrict__ b) {
    __shared__ float sA[16][HH];
    int r0 = blockIdx.x*16, c = threadIdx.x;
    float scc = g_sc[c], shc = g_sh[c];
    for (int rr = 0; rr < 16; rr++)
        sA[rr][c] = g_z[(r0+rr)*HH + c]*scc + shc;
    __syncthreads();
    float acc[16];
    float bc = b[c];
    #pragma unroll
    for (int rr = 0; rr < 16; rr++) acc[rr] = bc;
    for (int k = 0; k < HH; k++) {
        float w = W[k*HH + c];
        #pragma unroll
        for (int rr = 0; rr < 16; rr++) acc[rr] += sA[rr][k]*w;
    }
    for (int rr = 0; rr < 16; rr++) g_h[(r0+rr)*HH + c] = acc[rr];
}

// g_u = g_h + A @ g_h
__global__ void k_agg() {
    __shared__ int snb[MAXD];
    __shared__ int sdeg;
    int i = blockIdx.x, f = threadIdx.x;
    if (f == 0) sdeg = g_deg[i];
    __syncthreads();
    int dg = sdeg; if (dg > MAXD) dg = MAXD;
    for (int t = f; t < dg; t += HH) snb[t] = g_nbr[i*MAXD + t];
    __syncthreads();
    float acc = g_h[i*HH + f];
    for (int t = 0; t < dg; t++) acc += g_h[snb[t]*HH + f];
    g_u[i*HH + f] = acc;
}

// g_z = relu(g_u @ W + b)
__global__ void k_gemm_relu(const float* __restrict__ W, const float* __restrict__ b) {
    __shared__ float sA[16][HH];
    int r0 = blockIdx.x*16, c = threadIdx.x;
    for (int rr = 0; rr < 16; rr++)
        sA[rr][c] = g_u[(r0+rr)*HH + c];
    __syncthreads();
    float acc[16];
    float bc = b[c];
    #pragma unroll
    for (int rr = 0; rr < 16; rr++) acc[rr] = bc;
    for (int k = 0; k < HH; k++) {
        float w = W[k*HH + c];
        #pragma unroll
        for (int rr = 0; rr < 16; rr++) acc[rr] += sA[rr][k]*w;
    }
    for (int rr = 0; rr < 16; rr++) {
        float v = acc[rr];
        g_z[(r0+rr)*HH + c] = v > 0.f ? v : 0.f;
    }
}

__global__ void k_final(const float* __restrict__ w32, const float* __restrict__ b32) {
    int i = blockIdx.x*256 + threadIdx.x;
    if (i >= NN) return;
    float acc = b32[0];
    for (int k = 0; k < HH; k++)
        acc += (g_z[i*HH + k]*g_sc[k] + g_sh[k]) * w32[k];
    g_p[i] = 1.f / (1.f + expf(-acc));
}

// ---------------- loss ----------------
__global__ void k_loss() {
    __shared__ float r1[1024], r2[1024];
    int tid = threadIdx.x;
    float a = 0.f, b = 0.f;
    for (int i = tid; i < NN; i += 1024) {
        float pi = g_p[i];
        a += g_ent[i]*pi;
        int dg = g_deg[i]; if (dg > MAXD) dg = MAXD;
        float ap = 0.f;
        for (int t = 0; t < dg; t++) ap += g_p[g_nbr[i*MAXD + t]];
        b += pi*ap;
    }
    r1[tid] = a; r2[tid] = b; __syncthreads();
    for (int s = 512; s > 0; s >>= 1) {
        if (tid < s) { r1[tid] += r1[tid+s]; r2[tid] += r2[tid+s]; }
        __syncthreads();
    }
    if (tid == 0) g_loss = g_gamma - r1[0] + r2[0];
}

// ---------------- stable sort by (-p, idx) + sequential greedy ----------------
__global__ void k_sort_greedy() {
    __shared__ unsigned long long skey[NN];   // 16KB
    __shared__ float sdum[NN];                // 8KB
    __shared__ float sent[NN];                // 8KB
    __shared__ float red[1024], red2[1024];   // 8KB
    __shared__ unsigned srow[NWRD], ssel[NWRD], srej[NWRD], sdz[NWRD];
    __shared__ int s_idx, s_t, s_accept;

    int tid = threadIdx.x;
    for (int i = tid; i < NN; i += 1024) {
        float pv = g_p[i];
        unsigned pb = __float_as_uint(pv);
        skey[i] = ((unsigned long long)(0xFFFFFFFFu - pb) << 32) | (unsigned long long)i;
        sdum[i] = pv;
        sent[i] = g_ent[i];
    }
    if (tid < NWRD) {
        ssel[tid] = 0u; srej[tid] = 0u;
        unsigned m = 0u;
        for (int b = 0; b < 32; b++) if (g_deg[tid*32 + b] == 0) m |= 1u << b;
        sdz[tid] = m;
    }
    if (tid == 0) s_t = 0;
    __syncthreads();

    // bitonic sort, ascending key  (== descending p, ties by index ascending)
    for (int k = 2; k <= NN; k <<= 1) {
        for (int j = k >> 1; j > 0; j >>= 1) {
            for (int off = 0; off < NN; off += 1024) {
                int i = tid + off;
                int l = i ^ j;
                if (l > i) {
                    bool up = ((i & k) == 0);
                    unsigned long long a = skey[i], b = skey[l];
                    if ((a > b) == up) { skey[i] = b; skey[l] = a; }
                }
            }
            __syncthreads();
        }
    }

    float gamma = g_gamma;
    float loss  = g_loss;
    int nE = g_nedges;

    while (true) {
        __syncthreads();
        if (tid == 0) {
            int t = s_t, found = -1;
            while (t < NN) {
                int idx = (int)(skey[t] & 0xFFFFFFFFull);
                int w = idx >> 5; unsigned bit = 1u << (idx & 31);
                if (sdz[w] & bit) { ssel[w] |= bit; t++; continue; }   // isolated -> select
                if ((ssel[w] | srej[w]) & bit) { t++; continue; }       // ineligible -> skip
                found = idx; break;
            }
            s_idx = found; s_t = t + 1;
        }
        __syncthreads();
        int idx = s_idx;
        if (idx < 0) break;

        if (tid < NWRD) srow[tid] = g_adj[idx*NWRD + tid];
        __syncthreads();

        float ea = 0.f, qa = 0.f;
        for (int u = tid; u < NN; u += 1024) {
            float su = (u == idx) ? 1.f : (((srow[u>>5] >> (u & 31)) & 1u) ? 0.f : sdum[u]);
            ea += sent[u]*su;
        }
        for (int e = tid; e < nE; e += 1024) {
            unsigned pr = g_edges[e];
            int u = pr >> 16, v = pr & 0xFFFF;
            float su = (u == idx) ? 1.f : (((srow[u>>5] >> (u & 31)) & 1u) ? 0.f : sdum[u]);
            float sv = (v == idx) ? 1.f : (((srow[v>>5] >> (v & 31)) & 1u) ? 0.f : sdum[v]);
            qa += su*sv;
        }
        red[tid] = ea; red2[tid] = qa; __syncthreads();
        for (int s = 512; s > 0; s >>= 1) {
            if (tid < s) { red[tid] += red[tid+s]; red2[tid] += red2[tid+s]; }
            __syncthreads();
        }
        if (tid == 0) {
            float li = gamma - red[0] + red2[0];
            s_accept = (li <= loss) ? 1 : 0;
            if (s_accept) ssel[idx>>5] |= 1u << (idx & 31);
        }
        __syncthreads();
        if (s_accept) {
            if (tid < NWRD) srej[tid] |= srow[tid];
            for (int u = tid; u < NN; u += 1024)
                if ((srow[u>>5] >> (u & 31)) & 1u) sdum[u] = 0.f;
            if (tid == 0) sdum[idx] = 1.f;
        }
    }
    if (tid < NWRD) g_sel[tid] = ssel[tid];
}

// ---------------- boolean adjacency powers ----------------
// phase 0: g_B2[i] = OR_{j in nb(i)} g_adj[j]   (reach in exactly 2 steps)
// phase 1: g_B3[i] = OR_{j in nb(i)} g_B2[j]    (reach in exactly 3 steps)
__global__ void k_bool(int phase) {
    __shared__ int snb[MAXD];
    __shared__ int sdeg;
    int i = blockIdx.x, w = threadIdx.x;
    if (w == 0) sdeg = g_deg[i];
    __syncthreads();
    int dg = sdeg; if (dg > MAXD) dg = MAXD;
    for (int t = w; t < dg; t += NWRD) snb[t] = g_nbr[i*MAXD + t];
    __syncthreads();
    unsigned acc = 0u;
    if (phase == 0) {
        for (int t = 0; t < dg; t++) acc |= g_adj[snb[t]*NWRD + w];
        g_B2[i*NWRD + w] = acc;
    } else {
        for (int t = 0; t < dg; t++) acc |= g_B2[snb[t]*NWRD + w];
        g_B3[i*NWRD + w] = acc;
    }
}

// ---------------- output assembly ----------------
__global__ void k_out(float* __restrict__ out, const float* __restrict__ x,
                      const int* __restrict__ batch, int out_size) {
    const int XP  = NN*DD;                 // 524288
    const int AE  = XP + NN*NN;            // 4718592
    const int SE  = AE + NN;               // 4720640
    const int BE  = SE + NN;               // 4722688
    int idx = blockIdx.x*256 + threadIdx.x;
    if (idx >= out_size) return;
    if (idx < XP) {
        int i = idx >> 8;   // DD = 256
        bool s = (g_sel[i>>5] >> (i & 31)) & 1u;
        out[idx] = s ? x[idx] : 0.f;
    } else if (idx < AE) {
        int e = idx - XP;
        int i = e >> 11, j = e & 2047;
        unsigned b = ((g_B2[i*NWRD + (j>>5)] | g_B3[i*NWRD + (j>>5)]) >> (j & 31)) & 1u;
        bool si = (g_sel[i>>5] >> (i & 31)) & 1u;
        bool sj = (g_sel[j>>5] >> (j & 31)) & 1u;
        out[idx] = ((i != j) && b && si && sj) ? 1.f : 0.f;
    } else if (idx < SE) {
        int i = idx - AE;
        out[idx] = ((g_sel[i>>5] >> (i & 31)) & 1u) ? 1.f : 0.f;
    } else if (idx < BE) {
        int i = idx - SE;
        out[idx] = ((g_sel[i>>5] >> (i & 31)) & 1u) ? (float)batch[i] : -1.f;
    } else {
        out[idx] = g_loss;
    }
}

// ---------------- launch ----------------
extern "C" void kernel_launch(void* const* d_in, const int* in_sizes, int n_in,
                              void* d_out, int out_size) {
    const float* x   = (const float*)d_in[0];
    const int*   ei  = (const int*)  d_in[1];
    const int*   bat = (const int*)  d_in[2];
    const float* w11 = (const float*)d_in[3];
    const float* b11 = (const float*)d_in[4];
    const float* g1  = (const float*)d_in[5];
    const float* be1 = (const float*)d_in[6];
    const float* w12 = (const float*)d_in[7];
    const float* b12 = (const float*)d_in[8];
    const float* w21 = (const float*)d_in[9];
    const float* b21 = (const float*)d_in[10];
    const float* g2  = (const float*)d_in[11];
    const float* be2 = (const float*)d_in[12];
    const float* w22 = (const float*)d_in[13];
    const float* b22 = (const float*)d_in[14];
    const float* w31 = (const float*)d_in[15];
    const float* b31 = (const float*)d_in[16];
    const float* g3  = (const float*)d_in[17];
    const float* be3 = (const float*)d_in[18];
    const float* w32 = (const float*)d_in[19];
    const float* b32 = (const float*)d_in[20];
    float* out = (float*)d_out;

    // adjacency
    k_zero_adj<<<(NN*NWRD + 255)/256, 256>>>();
    k_build_adj<<<(32768 + 255)/256, 256>>>(ei);
    k_post<<<NN/256, 256>>>();
    k_scan<<<1, 1024>>>();
    k_fill_edges<<<NN/256, 256>>>();

    // entropy
    k_V<<<NN, DD>>>(x);
    k_softmax<<<1, 1024>>>(bat);

    // GIN layer 1
    k_agg1<<<NN/256, 256>>>();
    k_lin1<<<(NN*HH + 255)/256, 256>>>(w11, b11);
    k_bnstats<<<HH, 256>>>(g1, be1);
    k_gemm2<<<NN/16, HH>>>(w12, b12);

    // GIN layer 2
    k_agg<<<NN, HH>>>();
    k_gemm_relu<<<NN/16, HH>>>(w21, b21);
    k_bnstats<<<HH, 256>>>(g2, be2);
    k_gemm2<<<NN/16, HH>>>(w22, b22);

    // GIN layer 3
    k_agg<<<NN, HH>>>();
    k_gemm_relu<<<NN/16, HH>>>(w31, b31);
    k_bnstats<<<HH, 256>>>(g3, be3);
    k_final<<<NN/256, 256>>>(w32, b32);

    // loss + greedy selection
    k_loss<<<1, 1024>>>();
    k_sort_greedy<<<1, 1024>>>();

    // boolean A^2, A^3
    k_bool<<<NN, NWRD>>>(0);
    k_bool<<<NN, NWRD>>>(1);

    // outputs
    k_out<<<(out_size + 255)/256, 256>>>(out, x, bat, out_size);
}

// round 3
// speedup vs baseline: 1.1575x; 1.1575x over previous
#include <cuda_runtime.h>
#include <math.h>

#define NN 2048
#define DD 256
#define HH 128
#define GG 8
#define MAXD 128
#define NWRD 64   // 32-bit words per adjacency row (2048 bits)

// ---------------- device scratch (static, no runtime allocation) ----------------
static __device__ unsigned g_adj[NN*NWRD];
static __device__ int      g_deg[NN];
static __device__ int      g_nbr[NN*MAXD];
static __device__ float    g_V[NN];
static __device__ float    g_ent[NN];
static __device__ float    g_p[NN];
static __device__ float    g_a1[NN];
static __device__ float    g_u[NN*HH];
static __device__ float    g_z[NN*HH];
static __device__ float    g_h[NN*HH];
static __device__ float    g_sc[HH];
static __device__ float    g_sh[HH];
static __device__ float    g_gamma;
static __device__ float    g_loss;
static __device__ unsigned g_sel[NWRD];
static __device__ unsigned g_B2[NN*NWRD];
static __device__ unsigned g_B3[NN*NWRD];

// ---------------- adjacency build ----------------
__global__ void k_zero_adj() {
    int i = blockIdx.x*256 + threadIdx.x;
    if (i < NN*NWRD) g_adj[i] = 0u;
}

__global__ void k_build_adj(const int* __restrict__ ei) {
    int e = blockIdx.x*256 + threadIdx.x;
    if (e >= 32768) return;            // 32768 directed entries (both directions present)
    int u = ei[e];
    int v = ei[32768 + e];
    atomicOr(&g_adj[u*NWRD + (v>>5)], 1u << (v & 31));
}

__global__ void k_post() {
    int i = blockIdx.x*256 + threadIdx.x;
    if (i >= NN) return;
    int cnt = 0;
    for (int w = 0; w < NWRD; w++) {
        unsigned m = g_adj[i*NWRD + w];
        while (m) {
            int b = __ffs(m) - 1;
            m &= m - 1;
            if (cnt < MAXD) g_nbr[i*MAXD + cnt] = w*32 + b;
            cnt++;
        }
    }
    g_deg[i] = cnt;
}

// ---------------- V (entropy pre-term) ----------------
__global__ void k_V(const float* __restrict__ x) {
    __shared__ int   snb[MAXD];
    __shared__ int   sdeg;
    __shared__ float red[DD];
    int i = blockIdx.x;
    int d = threadIdx.x;
    if (d == 0) sdeg = g_deg[i];
    __syncthreads();
    int dg = sdeg; if (dg > MAXD) dg = MAXD;
    for (int t = d; t < dg; t += DD) snb[t] = g_nbr[i*MAXD + t];
    __syncthreads();
    float xi = x[i*DD + d];
    float ax = 0.f, axx = 0.f;
    for (int t = 0; t < dg; t++) {
        float v = x[snb[t]*DD + d];
        ax  += v;
        axx += v*v;
    }
    float tt = (float)sdeg*xi*xi - 2.f*xi*ax + axx;
    red[d] = tt*tt;
    __syncthreads();
    for (int s = DD/2; s > 0; s >>= 1) {
        if (d < s) red[d] += red[d+s];
        __syncthreads();
    }
    if (d == 0) g_V[i] = sqrtf(red[0]);
}

// ---------------- per-graph softmax -> ent, gamma ----------------
__global__ void k_softmax(const int* __restrict__ batch) {
    __shared__ float sV[NN];
    __shared__ float red[1024];
    __shared__ unsigned char sB[NN];
    __shared__ float gmax[GG], gsum[GG];
    int tid = threadIdx.x;
    for (int i = tid; i < NN; i += 1024) { sV[i] = g_V[i]; sB[i] = (unsigned char)batch[i]; }
    __syncthreads();
    for (int g = 0; g < GG; g++) {
        float m = -1e30f;
        for (int i = tid; i < NN; i += 1024) if (sB[i] == g) m = fmaxf(m, sV[i]);
        red[tid] = m; __syncthreads();
        for (int s = 512; s > 0; s >>= 1) { if (tid < s) red[tid] = fmaxf(red[tid], red[tid+s]); __syncthreads(); }
        if (tid == 0) gmax[g] = red[0];
        __syncthreads();
    }
    for (int i = tid; i < NN; i += 1024) sV[i] = expf(sV[i] - gmax[sB[i]]);
    __syncthreads();
    for (int g = 0; g < GG; g++) {
        float s = 0.f;
        for (int i = tid; i < NN; i += 1024) if (sB[i] == g) s += sV[i];
        red[tid] = s; __syncthreads();
        for (int st = 512; st > 0; st >>= 1) { if (tid < st) red[tid] += red[tid+st]; __syncthreads(); }
        if (tid == 0) gsum[g] = red[0];
        __syncthreads();
    }
    float acc = 0.f;
    for (int i = tid; i < NN; i += 1024) {
        float P = sV[i] / gsum[sB[i]];
        float e = (P == 0.f) ? 0.f : -P*logf(P);
        g_ent[i] = e;
        acc += e;
    }
    red[tid] = acc; __syncthreads();
    for (int s = 512; s > 0; s >>= 1) { if (tid < s) red[tid] += red[tid+s]; __syncthreads(); }
    if (tid == 0) g_gamma = red[0];
}

// ---------------- GIN layers ----------------
__global__ void k_agg1() { // a1 = ent + A@ent  (scalar per node)
    int i = blockIdx.x*256 + threadIdx.x;
    if (i >= NN) return;
    int dg = g_deg[i]; if (dg > MAXD) dg = MAXD;
    float a = g_ent[i];
    for (int t = 0; t < dg; t++) a += g_ent[g_nbr[i*MAXD + t]];
    g_a1[i] = a;
}

__global__ void k_lin1(const float* __restrict__ w11, const float* __restrict__ b11) {
    int idx = blockIdx.x*256 + threadIdx.x;
    if (idx >= NN*HH) return;
    int i = idx >> 7, c = idx & 127;
    float v = g_a1[i]*w11[c] + b11[c];
    g_z[idx] = v > 0.f ? v : 0.f;
}

__global__ void k_bnstats(const float* __restrict__ g, const float* __restrict__ be) {
    __shared__ float red[256];
    __shared__ float mu_s;
    int c = blockIdx.x, tid = threadIdx.x;
    float s = 0.f;
    for (int r = tid; r < NN; r += 256) s += g_z[r*HH + c];
    red[tid] = s; __syncthreads();
    for (int st = 128; st > 0; st >>= 1) { if (tid < st) red[tid] += red[tid+st]; __syncthreads(); }
    if (tid == 0) mu_s = red[0] / (float)NN;
    __syncthreads();
    float mu = mu_s;
    float s2 = 0.f;
    for (int r = tid; r < NN; r += 256) { float d = g_z[r*HH + c] - mu; s2 += d*d; }
    red[tid] = s2; __syncthreads();
    for (int st = 128; st > 0; st >>= 1) { if (tid < st) red[tid] += red[tid+st]; __syncthreads(); }
    if (tid == 0) {
        float var = red[0] / (float)NN;
        float inv = 1.f / sqrtf(var + 1e-5f);
        float sc  = g[c]*inv;
        g_sc[c] = sc;
        g_sh[c] = be[c] - mu*sc;
    }
}

__global__ void k_gemm2(const float* __restrict__ W, const float* __restrict__ b) {
    __shared__ float sA[16][HH];
    int r0 = blockIdx.x*16, c = threadIdx.x;
    float scc = g_sc[c], shc = g_sh[c];
    for (int rr = 0; rr < 16; rr++)
        sA[rr][c] = g_z[(r0+rr)*HH + c]*scc + shc;
    __syncthreads();
    float acc[16];
    float bc = b[c];
    #pragma unroll
    for (int rr = 0; rr < 16; rr++) acc[rr] = bc;
    for (int k = 0; k < HH; k++) {
        float w = W[k*HH + c];
        #pragma unroll
        for (int rr = 0; rr < 16; rr++) acc[rr] += sA[rr][k]*w;
    }
    for (int rr = 0; rr < 16; rr++) g_h[(r0+rr)*HH + c] = acc[rr];
}

__global__ void k_agg() {
    __shared__ int snb[MAXD];
    __shared__ int sdeg;
    int i = blockIdx.x, f = threadIdx.x;
    if (f == 0) sdeg = g_deg[i];
    __syncthreads();
    int dg = sdeg; if (dg > MAXD) dg = MAXD;
    for (int t = f; t < dg; t += HH) snb[t] = g_nbr[i*MAXD + t];
    __syncthreads();
    float acc = g_h[i*HH + f];
    for (int t = 0; t < dg; t++) acc += g_h[snb[t]*HH + f];
    g_u[i*HH + f] = acc;
}

__global__ void k_gemm_relu(const float* __restrict__ W, const float* __restrict__ b) {
    __shared__ float sA[16][HH];
    int r0 = blockIdx.x*16, c = threadIdx.x;
    for (int rr = 0; rr < 16; rr++)
        sA[rr][c] = g_u[(r0+rr)*HH + c];
    __syncthreads();
    float acc[16];
    float bc = b[c];
    #pragma unroll
    for (int rr = 0; rr < 16; rr++) acc[rr] = bc;
    for (int k = 0; k < HH; k++) {
        float w = W[k*HH + c];
        #pragma unroll
        for (int rr = 0; rr < 16; rr++) acc[rr] += sA[rr][k]*w;
    }
    for (int rr = 0; rr < 16; rr++) {
        float v = acc[rr];
        g_z[(r0+rr)*HH + c] = v > 0.f ? v : 0.f;
    }
}

__global__ void k_final(const float* __restrict__ w32, const float* __restrict__ b32) {
    int i = blockIdx.x*256 + threadIdx.x;
    if (i >= NN) return;
    float acc = b32[0];
    for (int k = 0; k < HH; k++)
        acc += (g_z[i*HH + k]*g_sc[k] + g_sh[k]) * w32[k];
    g_p[i] = 1.f / (1.f + expf(-acc));
}

// ---------------- sort + greedy with incremental delta evaluation ----------------
__global__ void k_sort_greedy() {
    __shared__ unsigned long long skey[NN];   // 16KB
    __shared__ float sdum[NN];                // 8KB  (dummy vector d)
    __shared__ float sent[NN];                // 8KB
    __shared__ float sr[NN];                  // 8KB  (r_u = sum_{v in nb(u)} d_v)
    __shared__ short sdg[NN];                 // 4KB
    __shared__ int   cnb[MAXD];
    __shared__ unsigned srow[NWRD], ssel[NWRD], srej[NWRD], sdz[NWRD];
    __shared__ double partE[32], partQ[32];

    int tid = threadIdx.x;
    for (int i = tid; i < NN; i += 1024) {
        float pv = g_p[i];
        skey[i] = ((unsigned long long)(0xFFFFFFFFu - __float_as_uint(pv)) << 32) | (unsigned long long)i;
        sdum[i] = pv;
        sent[i] = g_ent[i];
        int dg = g_deg[i]; if (dg > MAXD) dg = MAXD;
        sdg[i] = (short)dg;
    }
    if (tid < NWRD) {
        ssel[tid] = 0u; srej[tid] = 0u;
        unsigned m = 0u;
        for (int b = 0; b < 32; b++) if (g_deg[tid*32 + b] == 0) m |= 1u << b;
        sdz[tid] = m;
    }
    __syncthreads();

    // r_u = neighbor-sum of d (deterministic per-node order)
    for (int i = tid; i < NN; i += 1024) {
        int dg = sdg[i];
        float acc = 0.f;
        for (int t = 0; t < dg; t++) acc += sdum[g_nbr[i*MAXD + t]];
        sr[i] = acc;
    }
    __syncthreads();

    // E0 = ent . d,  Q0 = d^T A d = sum d_u r_u   (double)
    {
        double e = 0.0, q = 0.0;
        for (int i = tid; i < NN; i += 1024) {
            e += (double)sent[i] * (double)sdum[i];
            q += (double)sdum[i] * (double)sr[i];
        }
        for (int o = 16; o > 0; o >>= 1) {
            e += __shfl_down_sync(0xffffffffu, e, o);
            q += __shfl_down_sync(0xffffffffu, q, o);
        }
        if ((tid & 31) == 0) { partE[tid >> 5] = e; partQ[tid >> 5] = q; }
    }
    __syncthreads();

    // bitonic sort ascending key  (== descending p, ties by index ascending)
    for (int k = 2; k <= NN; k <<= 1) {
        for (int j = k >> 1; j > 0; j >>= 1) {
            for (int off = 0; off < NN; off += 1024) {
                int i = tid + off;
                int l = i ^ j;
                if (l > i) {
                    bool up = ((i & k) == 0);
                    unsigned long long a = skey[i], b = skey[l];
                    if ((a > b) == up) { skey[i] = b; skey[l] = a; }
                }
            }
            __syncthreads();
        }
    }

    if (tid >= 32) return;   // greedy runs on warp 0 only

    double E, Q;
    {
        double ee = partE[tid], qq = partQ[tid];
        for (int o = 16; o > 0; o >>= 1) {
            ee += __shfl_down_sync(0xffffffffu, ee, o);
            qq += __shfl_down_sync(0xffffffffu, qq, o);
        }
        E = __shfl_sync(0xffffffffu, ee, 0);
        Q = __shfl_sync(0xffffffffu, qq, 0);
    }
    double gamma = (double)g_gamma;
    double lossd = gamma - E + Q;
    if (tid == 0) g_loss = (float)lossd;

    int t = 0;
    while (true) {
        int idx = -1;
        if (tid == 0) {
            while (t < NN) {
                int cand = (int)(skey[t] & 0xFFFFFFFFull);
                int w = cand >> 5; unsigned bit = 1u << (cand & 31);
                if (sdz[w] & bit)            { ssel[w] |= bit; t++; continue; } // isolated -> select
                if ((ssel[w] | srej[w]) & bit) { t++; continue; }                // ineligible -> skip
                idx = cand; break;
            }
            t++;
        }
        idx = __shfl_sync(0xffffffffu, idx, 0);
        if (idx < 0) break;

        for (int w = tid; w < NWRD; w += 32) srow[w] = g_adj[idx*NWRD + w];
        __syncwarp();
        int m = sdg[idx];
        for (int k = tid; k < m; k += 32) cnb[k] = g_nbr[idx*MAXD + k];
        __syncwarp();

        double dI = 1.0 - (double)sdum[idx];   // delta at idx
        double dE = 0.0, dR = 0.0, rho0 = 0.0, dRho = 0.0;
        for (int k = tid; k < m; k += 32) {
            int u = cnb[k];
            float duf = sdum[u];
            if (duf != 0.f) {
                double du = -(double)duf;      // delta at neighbor u
                dE   += du * (double)sent[u];
                dR   += du * (double)sr[u];
                rho0 += du;
                double rho = 0.0;              // rho_u = sum_{v in nb(u) & C} delta_v
                int dgu = sdg[u];
                const int* nb = &g_nbr[u*MAXD];
                for (int j = 0; j < dgu; j++) {
                    int v = nb[j];
                    if (v == idx) rho += dI;
                    else if ((srow[v>>5] >> (v & 31)) & 1u) rho -= (double)sdum[v];
                }
                dRho += du * rho;
            }
        }
        for (int o = 16; o > 0; o >>= 1) {
            dE   += __shfl_down_sync(0xffffffffu, dE,   o);
            dR   += __shfl_down_sync(0xffffffffu, dR,   o);
            rho0 += __shfl_down_sync(0xffffffffu, rho0, o);
            dRho += __shfl_down_sync(0xffffffffu, dRho, o);
        }
        int accept = 0;
        double dEt = 0.0, dQt = 0.0;
        if (tid == 0) {
            dEt = dI * (double)sent[idx] + dE;
            dQt = 2.0*(dI * (double)sr[idx] + dR) + dI*rho0 + dRho;
            double li = gamma - (E + dEt) + (Q + dQt);
            accept = (li <= lossd) ? 1 : 0;
        }
        accept = __shfl_sync(0xffffffffu, accept, 0);
        if (accept) {
            dEt = __shfl_sync(0xffffffffu, dEt, 0);
            dQt = __shfl_sync(0xffffffffu, dQt, 0);
            E += dEt; Q += dQt;
            if (tid == 0) ssel[idx>>5] |= 1u << (idx & 31);
            // update r (deterministic: sequential per changed node, lanes split targets)
            float fdI = (float)dI;
            for (int k = tid; k < m; k += 32) sr[cnb[k]] += fdI;   // u = idx
            __syncwarp();
            for (int k = 0; k < m; k++) {
                int u = cnb[k];
                float duf = sdum[u];
                if (duf != 0.f) {
                    int dgu = sdg[u];
                    const int* nb = &g_nbr[u*MAXD];
                    for (int j = tid; j < dgu; j += 32) sr[nb[j]] -= duf;
                }
                __syncwarp();
            }
            // apply d update
            for (int k = tid; k < m; k += 32) sdum[cnb[k]] = 0.f;
            if (tid == 0) sdum[idx] = 1.f;
            for (int w = tid; w < NWRD; w += 32) srej[w] |= srow[w];
            __syncwarp();
        }
    }
    for (int w = tid; w < NWRD; w += 32) g_sel[w] = ssel[w];
}

// ---------------- boolean adjacency powers ----------------
__global__ void k_bool(int phase) {
    __shared__ int snb[MAXD];
    __shared__ int sdeg;
    int i = blockIdx.x, w = threadIdx.x;
    if (w == 0) sdeg = g_deg[i];
    __syncthreads();
    int dg = sdeg; if (dg > MAXD) dg = MAXD;
    for (int t = w; t < dg; t += NWRD) snb[t] = g_nbr[i*MAXD + t];
    __syncthreads();
    unsigned acc = 0u;
    if (phase == 0) {
        for (int t = 0; t < dg; t++) acc |= g_adj[snb[t]*NWRD + w];
        g_B2[i*NWRD + w] = acc;
    } else {
        for (int t = 0; t < dg; t++) acc |= g_B2[snb[t]*NWRD + w];
        g_B3[i*NWRD + w] = acc;
    }
}

// ---------------- output assembly ----------------
__global__ void k_out(float* __restrict__ out, const float* __restrict__ x,
                      const int* __restrict__ batch, int out_size) {
    const int XP  = NN*DD;                 // 524288
    const int AE  = XP + NN*NN;            // 4718592
    const int SE  = AE + NN;               // 4720640
    const int BE  = SE + NN;               // 4722688
    int idx = blockIdx.x*256 + threadIdx.x;
    if (idx >= out_size) return;
    if (idx < XP) {
        int i = idx >> 8;   // DD = 256
        bool s = (g_sel[i>>5] >> (i & 31)) & 1u;
        out[idx] = s ? x[idx] : 0.f;
    } else if (idx < AE) {
        int e = idx - XP;
        int i = e >> 11, j = e & 2047;
        unsigned b = ((g_B2[i*NWRD + (j>>5)] | g_B3[i*NWRD + (j>>5)]) >> (j & 31)) & 1u;
        bool si = (g_sel[i>>5] >> (i & 31)) & 1u;
        bool sj = (g_sel[j>>5] >> (j & 31)) & 1u;
        out[idx] = ((i != j) && b && si && sj) ? 1.f : 0.f;
    } else if (idx < SE) {
        int i = idx - AE;
        out[idx] = ((g_sel[i>>5] >> (i & 31)) & 1u) ? 1.f : 0.f;
    } else if (idx < BE) {
        int i = idx - SE;
        out[idx] = ((g_sel[i>>5] >> (i & 31)) & 1u) ? (float)batch[i] : -1.f;
    } else {
        out[idx] = g_loss;
    }
}

// ---------------- launch ----------------
extern "C" void kernel_launch(void* const* d_in, const int* in_sizes, int n_in,
                              void* d_out, int out_size) {
    const float* x   = (const float*)d_in[0];
    const int*   ei  = (const int*)  d_in[1];
    const int*   bat = (const int*)  d_in[2];
    const float* w11 = (const float*)d_in[3];
    const float* b11 = (const float*)d_in[4];
    const float* g1  = (const float*)d_in[5];
    const float* be1 = (const float*)d_in[6];
    const float* w12 = (const float*)d_in[7];
    const float* b12 = (const float*)d_in[8];
    const float* w21 = (const float*)d_in[9];
    const float* b21 = (const float*)d_in[10];
    const float* g2  = (const float*)d_in[11];
    const float* be2 = (const float*)d_in[12];
    const float* w22 = (const float*)d_in[13];
    const float* b22 = (const float*)d_in[14];
    const float* w31 = (const float*)d_in[15];
    const float* b31 = (const float*)d_in[16];
    const float* g3  = (const float*)d_in[17];
    const float* be3 = (const float*)d_in[18];
    const float* w32 = (const float*)d_in[19];
    const float* b32 = (const float*)d_in[20];
    float* out = (float*)d_out;

    // adjacency
    k_zero_adj<<<(NN*NWRD + 255)/256, 256>>>();
    k_build_adj<<<(32768 + 255)/256, 256>>>(ei);
    k_post<<<NN/256, 256>>>();

    // entropy
    k_V<<<NN, DD>>>(x);
    k_softmax<<<1, 1024>>>(bat);

    // GIN layer 1
    k_agg1<<<NN/256, 256>>>();
    k_lin1<<<(NN*HH + 255)/256, 256>>>(w11, b11);
    k_bnstats<<<HH, 256>>>(g1, be1);
    k_gemm2<<<NN/16, HH>>>(w12, b12);

    // GIN layer 2
    k_agg<<<NN, HH>>>();
    k_gemm_relu<<<NN/16, HH>>>(w21, b21);
    k_bnstats<<<HH, 256>>>(g2, be2);
    k_gemm2<<<NN/16, HH>>>(w22, b22);

    // GIN layer 3
    k_agg<<<NN, HH>>>();
    k_gemm_relu<<<NN/16, HH>>>(w31, b31);
    k_bnstats<<<HH, 256>>>(g3, be3);
    k_final<<<NN/256, 256>>>(w32, b32);

    // sort + greedy (computes loss internally: loss = gamma - E0 + Q0)
    k_sort_greedy<<<1, 1024>>>();

    // boolean A^2, A^3
    k_bool<<<NN, NWRD>>>(0);
    k_bool<<<NN, NWRD>>>(1);

    // outputs
    k_out<<<(out_size + 255)/256, 256>>>(out, x, bat, out_size);
}